// round 5
// baseline (speedup 1.0000x reference)
#include <cuda_runtime.h>
#include <math.h>
#include <stdint.h>

#define NLEV 16
#define TSIZE (1u << 19)
#define NPTS (1 << 20)

struct Meta {
    float scale[NLEV];
    int   res[NLEV];
    unsigned hashed;   // bit l set => hashed level (res^3 > T)
};

// scratch: encoded features, transposed [NLEV][N] as float2 for coalescing
__device__ float2 g_enc[NLEV * NPTS];

// ---------- packed f32x2 helpers (Blackwell FFMA2 path) ----------
__device__ __forceinline__ unsigned long long dup2(float v) {
    unsigned long long r; unsigned u = __float_as_uint(v);
    asm("mov.b64 %0, {%1, %1};" : "=l"(r) : "r"(u));
    return r;
}
__device__ __forceinline__ unsigned long long fma2(unsigned long long a,
                                                   unsigned long long b,
                                                   unsigned long long c) {
    unsigned long long d;
    asm("fma.rn.f32x2 %0, %1, %2, %3;" : "=l"(d) : "l"(a), "l"(b), "l"(c));
    return d;
}
__device__ __forceinline__ void unpk(unsigned long long v, float& lo, float& hi) {
    unsigned a, b;
    asm("mov.b64 {%0, %1}, %2;" : "=r"(a), "=r"(b) : "l"(v));
    lo = __uint_as_float(a); hi = __uint_as_float(b);
}
__device__ __forceinline__ unsigned long long packf(float lo, float hi) {
    return ((unsigned long long)__float_as_uint(hi) << 32) |
            (unsigned long long)__float_as_uint(lo);
}

// softplus(10x)/10, stable logaddexp form (matches jax.nn.softplus)
__device__ __forceinline__ float softplus10(float x) {
    float y = 10.0f * x;
    return (fmaxf(y, 0.0f) + log1pf(__expf(-fabsf(y)))) * 0.1f;
}

// ============================================================
// Kernel 1: hash-grid encode (gather-bound, high occupancy)
// ============================================================
__global__ void __launch_bounds__(256)
encode_kernel(const float* __restrict__ x,
              const float* __restrict__ grid,
              int N, Meta meta) {
    const int i = blockIdx.x * blockDim.x + threadIdx.x;
    if (i >= N) return;

    const float px = x[3 * i + 0];
    const float py = x[3 * i + 1];
    const float pz = x[3 * i + 2];

    const float2* __restrict__ g2 = (const float2*)grid;

    #pragma unroll
    for (int l = 0; l < NLEV; l++) {
        const float s  = meta.scale[l];
        const int  res = meta.res[l];
        const bool hashed = (meta.hashed >> l) & 1u;

        float fx = fmaf(px, s, 0.5f);
        float fy = fmaf(py, s, 0.5f);
        float fz = fmaf(pz, s, 0.5f);
        float flx = floorf(fx), fly = floorf(fy), flz = floorf(fz);
        float rx = fx - flx, ry = fy - fly, rz = fz - flz;
        int gx = (int)flx, gy = (int)fly, gz = (int)flz;

        float wx[2] = {1.0f - rx, rx};
        float wy[2] = {1.0f - ry, ry};
        float wz[2] = {1.0f - rz, rz};

        float s0 = 0.0f, s1 = 0.0f;
        #pragma unroll
        for (int c = 0; c < 8; c++) {
            const int cx = c & 1, cy = (c >> 1) & 1, cz = (c >> 2) & 1;
            unsigned idx;
            if (hashed) {
                unsigned ux = (unsigned)(gx + cx);
                unsigned uy = (unsigned)(gy + cy);
                unsigned uz = (unsigned)(gz + cz);
                idx = (ux * 1u) ^ (uy * 2654435761u) ^ (uz * 805459861u);
                idx &= (TSIZE - 1u);
            } else {
                int ix = min(max(gx + cx, 0), res - 1);
                int iy = min(max(gy + cy, 0), res - 1);
                int iz = min(max(gz + cz, 0), res - 1);
                idx = (unsigned)(ix + res * (iy + res * iz));
            }
            float2 f = __ldg(&g2[(size_t)l * TSIZE + idx]);
            float w = wx[cx] * wy[cy] * wz[cz];
            s0 = fmaf(w, f.x, s0);
            s1 = fmaf(w, f.y, s1);
        }
        g_enc[(size_t)l * N + i] = make_float2(s0, s1);   // coalesced store
    }
}

// ============================================================
// Kernel 2: MLP 32 -> 64 -> 64 -> 64 -> 1  (f32x2 packed FMA)
// ============================================================
// w layout: [IN/2][32] ulonglong2; entry (k2, p):
//   .x = pack(W[2p][2k2],   W[2p+1][2k2])
//   .y = pack(W[2p][2k2+1], W[2p+1][2k2+1])
template<int IN>
__device__ __forceinline__ void dense64(const float (&act)[IN],
                                        const ulonglong2* __restrict__ w,
                                        float (&out)[64]) {
    unsigned long long acc[32];
    #pragma unroll
    for (int p = 0; p < 32; p++) acc[p] = 0ull;
    #pragma unroll
    for (int k2 = 0; k2 < IN / 2; k2++) {
        unsigned long long a0 = dup2(act[2 * k2 + 0]);
        unsigned long long a1 = dup2(act[2 * k2 + 1]);
        const ulonglong2* wr = w + k2 * 32;
        #pragma unroll
        for (int p = 0; p < 32; p++) {
            ulonglong2 wv = wr[p];
            acc[p] = fma2(a0, wv.x, acc[p]);
            acc[p] = fma2(a1, wv.y, acc[p]);
        }
    }
    #pragma unroll
    for (int p = 0; p < 32; p++) unpk(acc[p], out[2 * p], out[2 * p + 1]);
}

__global__ void __launch_bounds__(128)
mlp_kernel(const float* __restrict__ W1,
           const float* __restrict__ W2,
           const float* __restrict__ W3,
           const float* __restrict__ W4,
           float* __restrict__ out,
           int N) {
    __shared__ ulonglong2 sW1[16 * 32];   //  8 KB
    __shared__ ulonglong2 sW2[32 * 32];   // 16 KB
    __shared__ ulonglong2 sW3[32 * 32];   // 16 KB
    __shared__ float      sW4[64];

    const int tid = threadIdx.x;
    for (int t = tid; t < 16 * 32; t += blockDim.x) {
        int k2 = t >> 5, p = t & 31;
        int j0 = 2 * p, j1 = 2 * p + 1;
        int k0 = 2 * k2, k1 = 2 * k2 + 1;
        sW1[t] = make_ulonglong2(packf(W1[j0 * 32 + k0], W1[j1 * 32 + k0]),
                                 packf(W1[j0 * 32 + k1], W1[j1 * 32 + k1]));
    }
    for (int t = tid; t < 32 * 32; t += blockDim.x) {
        int k2 = t >> 5, p = t & 31;
        int j0 = 2 * p, j1 = 2 * p + 1;
        int k0 = 2 * k2, k1 = 2 * k2 + 1;
        sW2[t] = make_ulonglong2(packf(W2[j0 * 64 + k0], W2[j1 * 64 + k0]),
                                 packf(W2[j0 * 64 + k1], W2[j1 * 64 + k1]));
        sW3[t] = make_ulonglong2(packf(W3[j0 * 64 + k0], W3[j1 * 64 + k0]),
                                 packf(W3[j0 * 64 + k1], W3[j1 * 64 + k1]));
    }
    for (int t = tid; t < 64; t += blockDim.x) sW4[t] = W4[t];
    __syncthreads();

    const int i = blockIdx.x * blockDim.x + tid;
    if (i >= N) return;

    // load encoded features (coalesced float2 loads)
    float enc[32];
    #pragma unroll
    for (int l = 0; l < NLEV; l++) {
        float2 f = g_enc[(size_t)l * N + i];
        enc[2 * l + 0] = f.x;
        enc[2 * l + 1] = f.y;
    }

    float h1[64];
    dense64<32>(enc, sW1, h1);
    #pragma unroll
    for (int j = 0; j < 64; j++) h1[j] = softplus10(h1[j]);

    float h2[64];
    dense64<64>(h1, sW2, h2);
    #pragma unroll
    for (int j = 0; j < 64; j++) h2[j] = softplus10(h2[j]);

    float h3[64];
    dense64<64>(h2, sW3, h3);
    #pragma unroll
    for (int j = 0; j < 64; j++) h3[j] = softplus10(h3[j]);

    float sdf = 0.0f;
    #pragma unroll
    for (int k = 0; k < 64; k++) sdf = fmaf(h3[k], sW4[k], sdf);

    out[i] = sdf;
}

static Meta build_meta() {
    Meta m;
    m.hashed = 0u;
    const double b = pow(2.0, log2(2048.0 / 16.0) / 15.0);
    for (int l = 0; l < NLEV; l++) {
        double sc = 16.0 * pow(b, (double)l) - 1.0;
        int r = (int)ceil(sc) + 1;
        m.scale[l] = (float)sc;
        m.res[l] = r;
        long long r3 = (long long)r * r * r;
        if (r3 > (long long)TSIZE) m.hashed |= (1u << l);
    }
    return m;
}

extern "C" void kernel_launch(void* const* d_in, const int* in_sizes, int n_in,
                              void* d_out, int out_size) {
    const float* x    = (const float*)d_in[0];
    const float* grid = (const float*)d_in[1];
    const float* W1   = (const float*)d_in[2];
    const float* W2   = (const float*)d_in[3];
    const float* W3   = (const float*)d_in[4];
    const float* W4   = (const float*)d_in[5];
    float* out = (float*)d_out;

    const int N = in_sizes[0] / 3;
    Meta meta = build_meta();

    encode_kernel<<<(N + 255) / 256, 256>>>(x, grid, N, meta);
    mlp_kernel<<<(N + 127) / 128, 128>>>(W1, W2, W3, W4, out, N);
}

// round 7
// speedup vs baseline: 1.6902x; 1.6902x over previous
#include <cuda_runtime.h>
#include <math.h>
#include <stdint.h>

#define NLEV 16
#define TSIZE (1u << 19)
#define NPTS (1 << 20)

struct Meta {
    float scale[NLEV];
    int   res[NLEV];
    unsigned hashed;   // bit l set => hashed level (res^3 > T)
};

// scratch: encoded features, transposed [NLEV][N] as float2 for coalescing
__device__ float2 g_enc[NLEV * NPTS];

// ---------- packed f32x2 helpers ----------
__device__ __forceinline__ unsigned long long dup2(float v) {
    unsigned long long r; unsigned u = __float_as_uint(v);
    asm("mov.b64 %0, {%1, %1};" : "=l"(r) : "r"(u));
    return r;
}
__device__ __forceinline__ unsigned long long fma2(unsigned long long a,
                                                   unsigned long long b,
                                                   unsigned long long c) {
    unsigned long long d;
    asm("fma.rn.f32x2 %0, %1, %2, %3;" : "=l"(d) : "l"(a), "l"(b), "l"(c));
    return d;
}
__device__ __forceinline__ void unpk(unsigned long long v, float& lo, float& hi) {
    unsigned a, b;
    asm("mov.b64 {%0, %1}, %2;" : "=r"(a), "=r"(b) : "l"(v));
    lo = __uint_as_float(a); hi = __uint_as_float(b);
}
__device__ __forceinline__ unsigned long long packf(float lo, float hi) {
    return ((unsigned long long)__float_as_uint(hi) << 32) |
            (unsigned long long)__float_as_uint(lo);
}

// softplus(10x)/10, stable; fast __expf/__logf (abs err ~1e-6, fine at 1e-3 tol)
__device__ __forceinline__ float softplus10(float x) {
    float y = 10.0f * x;
    float t = __expf(-fabsf(y));
    return (fmaxf(y, 0.0f) + __logf(1.0f + t)) * 0.1f;
}

// ============================================================
// Kernel 1: hash-grid encode (unchanged; measured ~340us)
// ============================================================
__global__ void __launch_bounds__(256)
encode_kernel(const float* __restrict__ x,
              const float* __restrict__ grid,
              int N, Meta meta) {
    const int i = blockIdx.x * blockDim.x + threadIdx.x;
    if (i >= N) return;

    const float px = x[3 * i + 0];
    const float py = x[3 * i + 1];
    const float pz = x[3 * i + 2];

    const float2* __restrict__ g2 = (const float2*)grid;

    #pragma unroll
    for (int l = 0; l < NLEV; l++) {
        const float s  = meta.scale[l];
        const int  res = meta.res[l];
        const bool hashed = (meta.hashed >> l) & 1u;

        float fx = fmaf(px, s, 0.5f);
        float fy = fmaf(py, s, 0.5f);
        float fz = fmaf(pz, s, 0.5f);
        float flx = floorf(fx), fly = floorf(fy), flz = floorf(fz);
        float rx = fx - flx, ry = fy - fly, rz = fz - flz;
        int gx = (int)flx, gy = (int)fly, gz = (int)flz;

        float wx[2] = {1.0f - rx, rx};
        float wy[2] = {1.0f - ry, ry};
        float wz[2] = {1.0f - rz, rz};

        float s0 = 0.0f, s1 = 0.0f;
        #pragma unroll
        for (int c = 0; c < 8; c++) {
            const int cx = c & 1, cy = (c >> 1) & 1, cz = (c >> 2) & 1;
            unsigned idx;
            if (hashed) {
                unsigned ux = (unsigned)(gx + cx);
                unsigned uy = (unsigned)(gy + cy);
                unsigned uz = (unsigned)(gz + cz);
                idx = (ux * 1u) ^ (uy * 2654435761u) ^ (uz * 805459861u);
                idx &= (TSIZE - 1u);
            } else {
                int ix = min(max(gx + cx, 0), res - 1);
                int iy = min(max(gy + cy, 0), res - 1);
                int iz = min(max(gz + cz, 0), res - 1);
                idx = (unsigned)(ix + res * (iy + res * iz));
            }
            float2 f = __ldg(&g2[(size_t)l * TSIZE + idx]);
            float w = wx[cx] * wy[cy] * wz[cz];
            s0 = fmaf(w, f.x, s0);
            s1 = fmaf(w, f.y, s1);
        }
        g_enc[(size_t)l * N + i] = make_float2(s0, s1);   // coalesced store
    }
}

// ============================================================
// Kernel 2: MLP with SMEM-resident activations (column/thread)
// ============================================================
// Weight layout per layer: [IN/2][32] ulonglong2; entry (k2,p):
//   .x = (W[2p][2k2],   W[2p+1][2k2])     packed f32x2
//   .y = (W[2p][2k2+1], W[2p+1][2k2+1])
//
// smem partition (bytes):
//   sW1:   [0, 8192)        16*32 ulonglong2
//   sW2:   [8192, 24576)    32*32 ulonglong2
//   sW3:   [24576, 40960)   32*32 ulonglong2
//   sW4:   [40960, 41216)   64 floats
//   sAct:  [41216, 106752)  [64][256] floats (column tid = this thread's act)
#define MLP_THREADS 256
#define OFF_W1 0
#define OFF_W2 8192
#define OFF_W3 24576
#define OFF_W4 40960
#define OFF_ACT 41216
#define MLP_SMEM (OFF_ACT + 64 * MLP_THREADS * 4)

// One layer pass: acc over IN inputs from sAct rows, 64 outputs in acc[32].
template<int IN>
__device__ __forceinline__ void dense_pass(const float* __restrict__ sA, int tid,
                                           const ulonglong2* __restrict__ w,
                                           unsigned long long (&acc)[32]) {
    #pragma unroll
    for (int p = 0; p < 32; p++) acc[p] = 0ull;
    #pragma unroll 4
    for (int k2 = 0; k2 < IN / 2; k2++) {
        unsigned long long a0 = dup2(sA[(2 * k2 + 0) * MLP_THREADS + tid]);
        unsigned long long a1 = dup2(sA[(2 * k2 + 1) * MLP_THREADS + tid]);
        const ulonglong2* wr = w + k2 * 32;
        #pragma unroll
        for (int p = 0; p < 32; p++) {
            ulonglong2 wv = wr[p];
            acc[p] = fma2(a0, wv.x, acc[p]);
            acc[p] = fma2(a1, wv.y, acc[p]);
        }
    }
}

__global__ void __launch_bounds__(MLP_THREADS, 2)
mlp_kernel(const float* __restrict__ W1,
           const float* __restrict__ W2,
           const float* __restrict__ W3,
           const float* __restrict__ W4,
           float* __restrict__ out,
           int N) {
    extern __shared__ char smem[];
    ulonglong2* sW1 = (ulonglong2*)(smem + OFF_W1);
    ulonglong2* sW2 = (ulonglong2*)(smem + OFF_W2);
    ulonglong2* sW3 = (ulonglong2*)(smem + OFF_W3);
    float*      sW4 = (float*)(smem + OFF_W4);
    float*      sA  = (float*)(smem + OFF_ACT);

    const int tid = threadIdx.x;

    // cooperative weight staging (pair-packed)
    for (int t = tid; t < 16 * 32; t += MLP_THREADS) {
        int k2 = t >> 5, p = t & 31;
        int j0 = 2 * p, j1 = 2 * p + 1;
        int k0 = 2 * k2, k1 = 2 * k2 + 1;
        sW1[t] = make_ulonglong2(packf(W1[j0 * 32 + k0], W1[j1 * 32 + k0]),
                                 packf(W1[j0 * 32 + k1], W1[j1 * 32 + k1]));
    }
    for (int t = tid; t < 32 * 32; t += MLP_THREADS) {
        int k2 = t >> 5, p = t & 31;
        int j0 = 2 * p, j1 = 2 * p + 1;
        int k0 = 2 * k2, k1 = 2 * k2 + 1;
        sW2[t] = make_ulonglong2(packf(W2[j0 * 64 + k0], W2[j1 * 64 + k0]),
                                 packf(W2[j0 * 64 + k1], W2[j1 * 64 + k1]));
        sW3[t] = make_ulonglong2(packf(W3[j0 * 64 + k0], W3[j1 * 64 + k0]),
                                 packf(W3[j0 * 64 + k1], W3[j1 * 64 + k1]));
    }
    for (int t = tid; t < 64; t += MLP_THREADS) sW4[t] = W4[t];
    __syncthreads();

    const int i = blockIdx.x * MLP_THREADS + tid;
    if (i < N) {
        // stage encoded features into own smem column (coalesced gmem loads)
        #pragma unroll
        for (int l = 0; l < NLEV; l++) {
            float2 f = g_enc[(size_t)l * N + i];
            sA[(2 * l + 0) * MLP_THREADS + tid] = f.x;
            sA[(2 * l + 1) * MLP_THREADS + tid] = f.y;
        }

        unsigned long long acc[32];

        // layer 1: 32 -> 64, epilogue writes softplus back to own column
        dense_pass<32>(sA, tid, sW1, acc);
        #pragma unroll
        for (int p = 0; p < 32; p++) {
            float v0, v1; unpk(acc[p], v0, v1);
            sA[(2 * p + 0) * MLP_THREADS + tid] = softplus10(v0);
            sA[(2 * p + 1) * MLP_THREADS + tid] = softplus10(v1);
        }

        // layer 2: 64 -> 64
        dense_pass<64>(sA, tid, sW2, acc);
        #pragma unroll
        for (int p = 0; p < 32; p++) {
            float v0, v1; unpk(acc[p], v0, v1);
            sA[(2 * p + 0) * MLP_THREADS + tid] = softplus10(v0);
            sA[(2 * p + 1) * MLP_THREADS + tid] = softplus10(v1);
        }

        // layer 3: 64 -> 64, fused with final dot (W4) — h3 never materialized
        dense_pass<64>(sA, tid, sW3, acc);
        float sdf = 0.0f;
        #pragma unroll
        for (int p = 0; p < 32; p++) {
            float v0, v1; unpk(acc[p], v0, v1);
            sdf = fmaf(softplus10(v0), sW4[2 * p + 0], sdf);
            sdf = fmaf(softplus10(v1), sW4[2 * p + 1], sdf);
        }
        out[i] = sdf;
    }
}

static Meta build_meta() {
    Meta m;
    m.hashed = 0u;
    const double b = pow(2.0, log2(2048.0 / 16.0) / 15.0);
    for (int l = 0; l < NLEV; l++) {
        double sc = 16.0 * pow(b, (double)l) - 1.0;
        int r = (int)ceil(sc) + 1;
        m.scale[l] = (float)sc;
        m.res[l] = r;
        long long r3 = (long long)r * r * r;
        if (r3 > (long long)TSIZE) m.hashed |= (1u << l);
    }
    return m;
}

extern "C" void kernel_launch(void* const* d_in, const int* in_sizes, int n_in,
                              void* d_out, int out_size) {
    const float* x    = (const float*)d_in[0];
    const float* grid = (const float*)d_in[1];
    const float* W1   = (const float*)d_in[2];
    const float* W2   = (const float*)d_in[3];
    const float* W3   = (const float*)d_in[4];
    const float* W4   = (const float*)d_in[5];
    float* out = (float*)d_out;

    const int N = in_sizes[0] / 3;
    Meta meta = build_meta();

    // idempotent, non-stream-ordered: safe under graph capture
    cudaFuncSetAttribute(mlp_kernel,
                         cudaFuncAttributeMaxDynamicSharedMemorySize, MLP_SMEM);

    encode_kernel<<<(N + 255) / 256, 256>>>(x, grid, N, meta);
    mlp_kernel<<<(N + MLP_THREADS - 1) / MLP_THREADS, MLP_THREADS, MLP_SMEM>>>(
        W1, W2, W3, W4, out, N);
}

// round 8
// speedup vs baseline: 2.0411x; 1.2076x over previous
#include <cuda_runtime.h>
#include <math.h>
#include <stdint.h>

#define NLEV 16
#define TSIZE (1u << 19)
#define NPTS (1 << 20)

struct Meta {
    float scale[NLEV];
    int   res[NLEV];
    unsigned hashed;   // bit l set => hashed level (res^3 > T)
};

// scratch: encoded features, transposed [NLEV][N] as float2 for coalescing
__device__ float2 g_enc[NLEV * NPTS];

// ---------- packed f32x2 helpers ----------
__device__ __forceinline__ unsigned long long dup2(float v) {
    unsigned long long r; unsigned u = __float_as_uint(v);
    asm("mov.b64 %0, {%1, %1};" : "=l"(r) : "r"(u));
    return r;
}
__device__ __forceinline__ unsigned long long fma2(unsigned long long a,
                                                   unsigned long long b,
                                                   unsigned long long c) {
    unsigned long long d;
    asm("fma.rn.f32x2 %0, %1, %2, %3;" : "=l"(d) : "l"(a), "l"(b), "l"(c));
    return d;
}
__device__ __forceinline__ void unpk(unsigned long long v, float& lo, float& hi) {
    unsigned a, b;
    asm("mov.b64 {%0, %1}, %2;" : "=r"(a), "=r"(b) : "l"(v));
    lo = __uint_as_float(a); hi = __uint_as_float(b);
}
__device__ __forceinline__ unsigned long long packf(float lo, float hi) {
    return ((unsigned long long)__float_as_uint(hi) << 32) |
            (unsigned long long)__float_as_uint(lo);
}

// softplus(10x)/10, stable; fast __expf/__logf (abs err ~1e-6, fine at 1e-3 tol)
__device__ __forceinline__ float softplus10(float x) {
    float y = 10.0f * x;
    float t = __expf(-fabsf(y));
    return (fmaxf(y, 0.0f) + __logf(1.0f + t)) * 0.1f;
}

// ============================================================
// Kernel 1: hash-grid encode (unchanged; measured ~335us)
// ============================================================
__global__ void __launch_bounds__(256)
encode_kernel(const float* __restrict__ x,
              const float* __restrict__ grid,
              int N, Meta meta) {
    const int i = blockIdx.x * blockDim.x + threadIdx.x;
    if (i >= N) return;

    const float px = x[3 * i + 0];
    const float py = x[3 * i + 1];
    const float pz = x[3 * i + 2];

    const float2* __restrict__ g2 = (const float2*)grid;

    #pragma unroll
    for (int l = 0; l < NLEV; l++) {
        const float s  = meta.scale[l];
        const int  res = meta.res[l];
        const bool hashed = (meta.hashed >> l) & 1u;

        float fx = fmaf(px, s, 0.5f);
        float fy = fmaf(py, s, 0.5f);
        float fz = fmaf(pz, s, 0.5f);
        float flx = floorf(fx), fly = floorf(fy), flz = floorf(fz);
        float rx = fx - flx, ry = fy - fly, rz = fz - flz;
        int gx = (int)flx, gy = (int)fly, gz = (int)flz;

        float wx[2] = {1.0f - rx, rx};
        float wy[2] = {1.0f - ry, ry};
        float wz[2] = {1.0f - rz, rz};

        float s0 = 0.0f, s1 = 0.0f;
        #pragma unroll
        for (int c = 0; c < 8; c++) {
            const int cx = c & 1, cy = (c >> 1) & 1, cz = (c >> 2) & 1;
            unsigned idx;
            if (hashed) {
                unsigned ux = (unsigned)(gx + cx);
                unsigned uy = (unsigned)(gy + cy);
                unsigned uz = (unsigned)(gz + cz);
                idx = (ux * 1u) ^ (uy * 2654435761u) ^ (uz * 805459861u);
                idx &= (TSIZE - 1u);
            } else {
                int ix = min(max(gx + cx, 0), res - 1);
                int iy = min(max(gy + cy, 0), res - 1);
                int iz = min(max(gz + cz, 0), res - 1);
                idx = (unsigned)(ix + res * (iy + res * iz));
            }
            float2 f = __ldg(&g2[(size_t)l * TSIZE + idx]);
            float w = wx[cx] * wy[cy] * wz[cz];
            s0 = fmaf(w, f.x, s0);
            s1 = fmaf(w, f.y, s1);
        }
        g_enc[(size_t)l * N + i] = make_float2(s0, s1);   // coalesced store
    }
}

// ============================================================
// Kernel 2: MLP — output-split thread pairs, 2 points/thread
// ============================================================
// Weight layout per layer: [IN/2][32] ulonglong2; entry (k2,p):
//   .x = (W[2p][2k2],   W[2p+1][2k2])     packed f32x2
//   .y = (W[2p][2k2+1], W[2p+1][2k2+1])
// Thread t: j = t&127 (point pair j, j+128), ohalf = t>>7
//   computes output rows [ohalf*32, ohalf*32+32) for both points,
//   i.e. weight entries p in [ohalf*16, ohalf*16+16).
//
// smem partition (bytes):
//   sW1:   [0, 8192)        16*32 ulonglong2
//   sW2:   [8192, 24576)    32*32 ulonglong2
//   sW3:   [24576, 40960)   32*32 ulonglong2
//   sW4:   [40960, 41216)   64 floats
//   sAct:  [41216, 106752)  [64][256] floats (column = point within CTA)
#define MLP_THREADS 256
#define OFF_W1 0
#define OFF_W2 8192
#define OFF_W3 24576
#define OFF_W4 40960
#define OFF_ACT 41216
#define MLP_SMEM (OFF_ACT + 64 * MLP_THREADS * 4)

// One half-layer pass: 32 outputs (this thread's half) for 2 points.
template<int IN>
__device__ __forceinline__ void dense_half(const float* __restrict__ sA,
                                           int j, int ohalf,
                                           const ulonglong2* __restrict__ w,
                                           unsigned long long (&acc0)[16],
                                           unsigned long long (&acc1)[16]) {
    #pragma unroll
    for (int p = 0; p < 16; p++) { acc0[p] = 0ull; acc1[p] = 0ull; }
    #pragma unroll 4
    for (int k2 = 0; k2 < IN / 2; k2++) {
        unsigned long long a0p0 = dup2(sA[(2 * k2 + 0) * MLP_THREADS + j]);
        unsigned long long a1p0 = dup2(sA[(2 * k2 + 1) * MLP_THREADS + j]);
        unsigned long long a0p1 = dup2(sA[(2 * k2 + 0) * MLP_THREADS + j + 128]);
        unsigned long long a1p1 = dup2(sA[(2 * k2 + 1) * MLP_THREADS + j + 128]);
        const ulonglong2* wr = w + k2 * 32 + ohalf * 16;
        #pragma unroll
        for (int p = 0; p < 16; p++) {
            ulonglong2 wv = wr[p];
            acc0[p] = fma2(a0p0, wv.x, acc0[p]);
            acc0[p] = fma2(a1p0, wv.y, acc0[p]);
            acc1[p] = fma2(a0p1, wv.x, acc1[p]);
            acc1[p] = fma2(a1p1, wv.y, acc1[p]);
        }
    }
}

// epilogue: softplus + write both points' half-rows back to sA
__device__ __forceinline__ void epilogue_half(float* __restrict__ sA,
                                              int j, int ohalf,
                                              unsigned long long (&acc0)[16],
                                              unsigned long long (&acc1)[16]) {
    const int row0 = ohalf * 32;
    #pragma unroll
    for (int p = 0; p < 16; p++) {
        float v0, v1; unpk(acc0[p], v0, v1);
        sA[(row0 + 2 * p + 0) * MLP_THREADS + j] = softplus10(v0);
        sA[(row0 + 2 * p + 1) * MLP_THREADS + j] = softplus10(v1);
        float u0, u1; unpk(acc1[p], u0, u1);
        sA[(row0 + 2 * p + 0) * MLP_THREADS + j + 128] = softplus10(u0);
        sA[(row0 + 2 * p + 1) * MLP_THREADS + j + 128] = softplus10(u1);
    }
}

__global__ void __launch_bounds__(MLP_THREADS, 2)
mlp_kernel(const float* __restrict__ W1,
           const float* __restrict__ W2,
           const float* __restrict__ W3,
           const float* __restrict__ W4,
           float* __restrict__ out,
           int N) {
    extern __shared__ char smem[];
    ulonglong2* sW1 = (ulonglong2*)(smem + OFF_W1);
    ulonglong2* sW2 = (ulonglong2*)(smem + OFF_W2);
    ulonglong2* sW3 = (ulonglong2*)(smem + OFF_W3);
    float*      sW4 = (float*)(smem + OFF_W4);
    float*      sA  = (float*)(smem + OFF_ACT);

    const int tid = threadIdx.x;
    const int j = tid & 127;
    const int ohalf = tid >> 7;
    const int base = blockIdx.x * MLP_THREADS;

    // cooperative weight staging (pair-packed)
    for (int t = tid; t < 16 * 32; t += MLP_THREADS) {
        int k2 = t >> 5, p = t & 31;
        int j0 = 2 * p, j1 = 2 * p + 1;
        int k0 = 2 * k2, k1 = 2 * k2 + 1;
        sW1[t] = make_ulonglong2(packf(W1[j0 * 32 + k0], W1[j1 * 32 + k0]),
                                 packf(W1[j0 * 32 + k1], W1[j1 * 32 + k1]));
    }
    for (int t = tid; t < 32 * 32; t += MLP_THREADS) {
        int k2 = t >> 5, p = t & 31;
        int j0 = 2 * p, j1 = 2 * p + 1;
        int k0 = 2 * k2, k1 = 2 * k2 + 1;
        sW2[t] = make_ulonglong2(packf(W2[j0 * 64 + k0], W2[j1 * 64 + k0]),
                                 packf(W2[j0 * 64 + k1], W2[j1 * 64 + k1]));
        sW3[t] = make_ulonglong2(packf(W3[j0 * 64 + k0], W3[j1 * 64 + k0]),
                                 packf(W3[j0 * 64 + k1], W3[j1 * 64 + k1]));
    }
    if (tid < 64) sW4[tid] = W4[tid];

    // stage encoded features: ohalf selects level range (rows split 16/16)
    {
        const int lbeg = ohalf * 8;           // levels [lbeg, lbeg+8)
        #pragma unroll
        for (int dl = 0; dl < 8; dl++) {
            int l = lbeg + dl;
            int i0 = base + j, i1 = base + j + 128;
            float2 f0 = (i0 < N) ? g_enc[(size_t)l * N + i0] : make_float2(0.f, 0.f);
            float2 f1 = (i1 < N) ? g_enc[(size_t)l * N + i1] : make_float2(0.f, 0.f);
            sA[(2 * l + 0) * MLP_THREADS + j] = f0.x;
            sA[(2 * l + 1) * MLP_THREADS + j] = f0.y;
            sA[(2 * l + 0) * MLP_THREADS + j + 128] = f1.x;
            sA[(2 * l + 1) * MLP_THREADS + j + 128] = f1.y;
        }
    }
    __syncthreads();

    unsigned long long acc0[16], acc1[16];

    // layer 1: 32 -> 64
    dense_half<32>(sA, j, ohalf, sW1, acc0, acc1);
    __syncthreads();                       // reads done before overwrite
    epilogue_half(sA, j, ohalf, acc0, acc1);
    __syncthreads();

    // layer 2: 64 -> 64
    dense_half<64>(sA, j, ohalf, sW2, acc0, acc1);
    __syncthreads();
    epilogue_half(sA, j, ohalf, acc0, acc1);
    __syncthreads();

    // layer 3: 64 -> 64
    dense_half<64>(sA, j, ohalf, sW3, acc0, acc1);
    __syncthreads();
    epilogue_half(sA, j, ohalf, acc0, acc1);
    __syncthreads();

    // final dot: each thread handles one point (col tid)
    const int i = base + tid;
    if (i < N) {
        float sdf = 0.0f;
        #pragma unroll
        for (int k = 0; k < 64; k++)
            sdf = fmaf(sA[k * MLP_THREADS + tid], sW4[k], sdf);
        out[i] = sdf;
    }
}

static Meta build_meta() {
    Meta m;
    m.hashed = 0u;
    const double b = pow(2.0, log2(2048.0 / 16.0) / 15.0);
    for (int l = 0; l < NLEV; l++) {
        double sc = 16.0 * pow(b, (double)l) - 1.0;
        int r = (int)ceil(sc) + 1;
        m.scale[l] = (float)sc;
        m.res[l] = r;
        long long r3 = (long long)r * r * r;
        if (r3 > (long long)TSIZE) m.hashed |= (1u << l);
    }
    return m;
}

extern "C" void kernel_launch(void* const* d_in, const int* in_sizes, int n_in,
                              void* d_out, int out_size) {
    const float* x    = (const float*)d_in[0];
    const float* grid = (const float*)d_in[1];
    const float* W1   = (const float*)d_in[2];
    const float* W2   = (const float*)d_in[3];
    const float* W3   = (const float*)d_in[4];
    const float* W4   = (const float*)d_in[5];
    float* out = (float*)d_out;

    const int N = in_sizes[0] / 3;
    Meta meta = build_meta();

    // idempotent, non-stream-ordered: safe under graph capture
    cudaFuncSetAttribute(mlp_kernel,
                         cudaFuncAttributeMaxDynamicSharedMemorySize, MLP_SMEM);

    encode_kernel<<<(N + 255) / 256, 256>>>(x, grid, N, meta);
    mlp_kernel<<<(N + MLP_THREADS - 1) / MLP_THREADS, MLP_THREADS, MLP_SMEM>>>(
        W1, W2, W3, W4, out, N);
}